// round 16
// baseline (speedup 1.0000x reference)
#include <cuda_runtime.h>
#include <cuda_fp16.h>
#include <math.h>
#include <stdint.h>

#define B_    64
#define CIN_  256
#define HID_  256
#define COUT_ 10
#define EPS_  1e-5f

// ---------------------------------------------------------------------------
// Device globals (no runtime allocation allowed)
// ---------------------------------------------------------------------------
__device__ float g_kfeat[B_ * HID_ * 25];        // (64,256,5,5)
__device__ float g_sfeat[B_ * HID_ * 841];       // (64,256,29,29)
__device__ float g_h    [B_ * HID_ * 625];       // (64,256,25,25)
// fp16 weights pre-packed in m16n8k16 A-fragment order:
//   uint4[ (m16b * (K/16) + kchunk) * 32 + lane ]
__device__ __align__(16) uint4 g_wkA[16 * 144 * 32];
__device__ __align__(16) uint4 g_wsA[16 * 144 * 32];
__device__ __align__(16) uint4 g_wdA[16 * 48 * 32];
__device__ __align__(16) uint4 g_wh1A[16 * 16 * 32];
// fp16 packed (single) inputs: [icpair 128][b 64][HW]
__device__ __align__(16) uint32_t g_kinF[128 * 64 * 49];
__device__ __align__(16) uint32_t g_sinF[128 * 64 * 961];
// fp16 packed (single) activations: [kpair][n=40000]
__device__ __align__(16) uint32_t g_featF[384 * 40000];
__device__ __align__(16) uint32_t g_f2F [128 * 40000];

// ---------------------------------------------------------------------------
// PTX helpers (baseline ISA only; compiles for plain compute_103)
// ---------------------------------------------------------------------------
__device__ __forceinline__ void mma_f16(float* c, const uint32_t* a,
                                        const uint32_t* b) {
    asm volatile(
        "mma.sync.aligned.m16n8k16.row.col.f32.f16.f16.f32 "
        "{%0,%1,%2,%3}, {%4,%5,%6,%7}, {%8,%9}, {%0,%1,%2,%3};"
        : "+f"(c[0]), "+f"(c[1]), "+f"(c[2]), "+f"(c[3])
        : "r"(a[0]), "r"(a[1]), "r"(a[2]), "r"(a[3]), "r"(b[0]), "r"(b[1]));
}

__device__ __forceinline__ void ldm4(uint32_t* d, uint32_t addr) {
    asm volatile("ldmatrix.sync.aligned.m8n8.x4.shared.b16 {%0,%1,%2,%3}, [%4];"
                 : "=r"(d[0]), "=r"(d[1]), "=r"(d[2]), "=r"(d[3]) : "r"(addr));
}

__device__ __forceinline__ uint32_t smem_u32(const void* p) {
    uint32_t a;
    asm("{ .reg .u64 t; cvta.to.shared.u64 t, %1; cvt.u32.u64 %0, t; }"
        : "=r"(a) : "l"(p));
    return a;
}

__device__ __forceinline__ uint32_t pack2h(float a, float b) {
    __half2 H = __floats2half2_rn(a, b);
    return *reinterpret_cast<uint32_t*>(&H);
}

// ---------------------------------------------------------------------------
// Prep kernels
// ---------------------------------------------------------------------------
// w(oc,ic,3,3) -> A-fragment order, k = tap*256 + ic, K = 2304 (144 chunks)
__global__ void prep_w3_frag(const float* __restrict__ w,
                             uint4* __restrict__ of) {
    int idx = blockIdx.x * 256 + threadIdx.x;
    if (idx >= 16 * 144 * 32) return;
    int lane = idx & 31;
    int kc   = (idx >> 5) % 144;
    int m16b = (idx >> 5) / 144;
    int gid = lane >> 2, tig = lane & 3;
    uint32_t r[4];
#pragma unroll
    for (int rr = 0; rr < 4; rr++) {
        int row = m16b * 16 + gid + 8 * (rr & 1);
        int kp  = tig + 4 * (rr >> 1);
        int k0  = kc * 16 + kp * 2;
        int tap0 = k0 >> 8, ic0 = k0 & 255;
        int tap1 = (k0 + 1) >> 8, ic1 = (k0 + 1) & 255;
        r[rr] = pack2h(w[(size_t)row * 2304 + ic0 * 9 + tap0],
                       w[(size_t)row * 2304 + ic1 * 9 + tap1]);
    }
    of[idx] = make_uint4(r[0], r[1], r[2], r[3]);
}

// w(oc,K) -> A-fragment order, k = channel
template <int K>
__global__ void prep_w1_frag(const float* __restrict__ w,
                             uint4* __restrict__ of) {
    int idx = blockIdx.x * 256 + threadIdx.x;
    if (idx >= 16 * (K / 16) * 32) return;
    int lane = idx & 31;
    int kc   = (idx >> 5) % (K / 16);
    int m16b = (idx >> 5) / (K / 16);
    int gid = lane >> 2, tig = lane & 3;
    uint32_t r[4];
#pragma unroll
    for (int rr = 0; rr < 4; rr++) {
        int row = m16b * 16 + gid + 8 * (rr & 1);
        int k0  = kc * 16 + (tig + 4 * (rr >> 1)) * 2;
        r[rr] = pack2h(w[(size_t)row * K + k0], w[(size_t)row * K + k0 + 1]);
    }
    of[idx] = make_uint4(r[0], r[1], r[2], r[3]);
}

template <int HW>
__global__ void prep_in_f16(const float* __restrict__ in,
                            uint32_t* __restrict__ of) {
    int idx = blockIdx.x * 256 + threadIdx.x;
    if (idx >= 128 * 64 * HW) return;
    int p = idx / (64 * HW);
    int rem = idx - p * (64 * HW);
    int b = rem / HW, pix = rem - b * HW;
    const float* src = in + (size_t)b * 256 * HW + (2 * p) * HW + pix;
    of[idx] = pack2h(src[0], src[HW]);
}

// ---------------------------------------------------------------------------
// Tensor-core GEMM (fp16 x fp16, fp32 accum): C = A*B + BN (+ReLU).
// A: LDG.128 direct to fragment registers from pre-packed layout, rolling
//    one-k-chunk-ahead ping-pong (no A smem).
// B: LDG->reg->STS double buffer, K=64 per stage (36 stages for conv_s:
//    barriers + per-stage addressing ALU halved vs K=32).
// MODE 0: implicit-GEMM 3x3 conv. MODE 1: 1x1 conv.
// EPI 0: fp32 NCHW. EPI 1: packed fp16 [kpair][n].
// ---------------------------------------------------------------------------
template <int MODE, int HIN, int WIN, int KT, bool RELU, int EPI>
__global__ void __launch_bounds__(256, 2)
gemm_f16_kernel(const uint32_t* __restrict__ bF_src,
                const uint4* __restrict__ aFrag,
                const float* __restrict__ bn, float* __restrict__ out,
                uint16_t* __restrict__ outF) {
    constexpr int WOUT = WIN - 2;
    constexpr int PXB  = (MODE == 0) ? (HIN - 2) * WOUT : 625;
    constexpr int NP   = 64 * PXB;
    constexpr int HW   = HIN * WIN;
    constexpr int S    = KT / 64;            // 64-k stages
    constexpr int KC16 = KT / 16;            // 16-k chunks total
    constexpr int RSTR = 36;                 // 32 kpair words + 4 pad (16B mult)
    constexpr int TILE = 128 * RSTR;         // 4608 u32 = 18 KB
    constexpr int PLSTR = 64 * HW;

    extern __shared__ uint32_t smem[];
    const uint32_t smb = smem_u32(smem);

    const int tid  = threadIdx.x;
    const int warp = tid >> 5;
    const int lane = tid & 31;
    const int gid  = lane >> 2;
    const int tig  = lane & 3;
    const int wm   = warp >> 1;
    const int moff = wm * 32;
    const int noff = (warp & 1) * 64;

    const int oc0 = blockIdx.y * 128;
    const int p0  = blockIdx.x * 128;

    const int bRow = (lane & 7) + ((lane >> 4) & 1) * 8;
    const int bCol = ((lane >> 3) & 1) * 4;

    const int nloc  = tid & 127;
    const int nglob = p0 + nloc;
    const bool nvalid = (nglob < NP);
    int bbase = 0;
    if (MODE == 0) {
        int nn = nvalid ? nglob : 0;
        int b = nn / PXB; int rem = nn - b * PXB;
        int y = rem / WOUT; int x = rem - y * WOUT;
        bbase = b * HW + y * WIN + x;
    }

    float acc[2][8][4];
#pragma unroll
    for (int a = 0; a < 2; a++)
#pragma unroll
        for (int b = 0; b < 8; b++)
#pragma unroll
            for (int c = 0; c < 4; c++) acc[a][b][c] = 0.f;

    // B prefetch: 128 px x 32 kpair words = 4096 u32 / 256 thr = 4 uint4 tasks
    auto prefetchB = [&](int s, uint32_t v[4][4]) {
        int tapoff = 0, plane0 = 0;
        if (MODE == 0) {
            int tap = s >> 2; plane0 = (s & 3) * 32;
            tapoff = (tap / 3) * WIN + (tap % 3);
        }
#pragma unroll
        for (int i = 0; i < 4; i++) {
            int task = tid + 256 * i;
            int wg = (task >> 7) & 7;
#pragma unroll
            for (int j = 0; j < 4; j++) {
                int w = wg * 4 + j;
                long addr = (MODE == 0)
                    ? (long)(plane0 + w) * PLSTR + bbase + tapoff
                    : (long)(s * 32 + w) * 40000 + nglob;
                v[i][j] = nvalid ? __ldg(bF_src + addr) : 0u;
            }
        }
    };
    auto storeB = [&](int buf, uint32_t v[4][4]) {
#pragma unroll
        for (int i = 0; i < 4; i++) {
            int task = tid + 256 * i;
            int wg = (task >> 7) & 7;
            uint32_t* dst = &smem[buf * TILE + nloc * RSTR + wg * 4];
            *reinterpret_cast<uint4*>(dst) =
                make_uint4(v[i][0], v[i][1], v[i][2], v[i][3]);
        }
    };
    // A fragments for one 16-k chunk g: 2 coalesced LDG.128 per thread
    auto loadA = [&](uint4 af[2], int g) {
        int gg = (g < KC16) ? g : 0;   // clamp (value unused past end)
#pragma unroll
        for (int mf = 0; mf < 2; mf++) {
            size_t idx = ((size_t)(oc0 / 16 + wm * 2 + mf) * KC16 + gg) * 32 + lane;
            af[mf] = __ldg(aFrag + idx);
        }
    };

    // one 16-k chunk of mma against B buffer `smB`, A in af
    auto mma_chunk = [&](uint32_t smB, int kc, uint4 af[2]) {
#pragma unroll
        for (int nfp = 0; nfp < 4; nfp++) {
            uint32_t boff = ((noff + nfp * 16 + bRow) * RSTR + kc * 8 + bCol) * 4;
            uint32_t bf[4];
            ldm4(bf, smB + boff);
#pragma unroll
            for (int snf = 0; snf < 2; snf++) {
                int nf = nfp * 2 + snf;
#pragma unroll
                for (int mf = 0; mf < 2; mf++)
                    mma_f16(acc[mf][nf],
                            reinterpret_cast<uint32_t*>(&af[mf]),
                            &bf[2 * snf]);
            }
        }
    };

    // prologue
    uint4 afA[2], afB[2];
    {
        uint32_t v[4][4];
        prefetchB(0, v);
        storeB(0, v);
        loadA(afA, 0);
    }

    for (int s = 0; s < S; s++) {
        const int buf = s & 1;
        __syncthreads();

        const bool have = (s + 1 < S);
        uint32_t vpre[4][4];
        if (have) prefetchB(s + 1, vpre);

        const uint32_t smB = smb + buf * TILE * 4;
        const int g0 = s * 4;
        // rolling A ping-pong: load chunk g+1 while mma on chunk g
        loadA(afB, g0 + 1);  mma_chunk(smB, 0, afA);
        loadA(afA, g0 + 2);  mma_chunk(smB, 1, afB);
        loadA(afB, g0 + 3);  mma_chunk(smB, 2, afA);
        loadA(afA, g0 + 4);  mma_chunk(smB, 3, afB);

        if (have) storeB(buf ^ 1, vpre);
    }

    // epilogue
    __syncthreads();
    float* Cs = (float*)smem;                // 128 x 132 fp32 (67584 B)
#pragma unroll
    for (int mf = 0; mf < 2; mf++) {
#pragma unroll
        for (int nf = 0; nf < 8; nf++) {
            int m0 = moff + mf * 16 + gid;
            int nl = noff + nf * 8 + 2 * tig;
            *(float2*)&Cs[m0 * 132 + nl]       = make_float2(acc[mf][nf][0], acc[mf][nf][1]);
            *(float2*)&Cs[(m0 + 8) * 132 + nl] = make_float2(acc[mf][nf][2], acc[mf][nf][3]);
        }
    }
    __syncthreads();

    for (int t = warp; t < 128; t += 8) {
        const int oc = oc0 + t;
        const float g  = bn[oc];
        const float be = bn[256 + oc];
        const float mm = bn[512 + oc];
        const float vv = bn[768 + oc];
        const float inv  = g * rsqrtf(vv + EPS_);
        const float bias = be - mm * inv;
#pragma unroll
        for (int cc0 = 0; cc0 < 128; cc0 += 32) {
            int cc = cc0 + lane;
            int n = p0 + cc;
            if (n < NP) {
                float val = Cs[t * 132 + cc] * inv + bias;
                if (RELU) val = fmaxf(val, 0.f);
                if (EPI == 0) {
                    int b = n / PXB; int rq = n - b * PXB;
                    out[((size_t)(b * 256 + oc)) * PXB + rq] = val;
                } else {
                    __half hv = __float2half_rn(val);
                    outF[(size_t)(oc >> 1) * 80000 + n * 2 + (oc & 1)] =
                        *reinterpret_cast<uint16_t*>(&hv);
                }
            }
        }
    }
}

// ---------------------------------------------------------------------------
// Multi-scale depthwise xcorr, paired channels, single fp16 packed output.
// ---------------------------------------------------------------------------
__global__ void multixcorr_kernel(const float* __restrict__ s,
                                  const float* __restrict__ k,
                                  uint32_t* __restrict__ ff) {
    const int kp0 = blockIdx.x;   // 0..127
    const int b   = blockIdx.y;

    __shared__ float ss[2][841];
    __shared__ float kk[2][25];

    const float* sp = s + ((size_t)b * HID_ + 2 * kp0) * 841;
    const float* kp = k + ((size_t)b * HID_ + 2 * kp0) * 25;

    for (int i = threadIdx.x; i < 2 * 841; i += blockDim.x)
        ss[i / 841][i % 841] = sp[i];
    if (threadIdx.x < 50) kk[threadIdx.x / 25][threadIdx.x % 25] = kp[threadIdx.x];
    __syncthreads();

    for (int p = threadIdx.x; p < 625; p += blockDim.x) {
        const int y = p / 25, x = p - (p / 25) * 25;
        float f0[2], f1[2], f2[2];
#pragma unroll
        for (int h = 0; h < 2; h++) {
            float s_full = 0.f, s_in = 0.f;
#pragma unroll
            for (int dy = 0; dy < 5; dy++)
#pragma unroll
                for (int dx = 0; dx < 5; dx++) {
                    float vv = ss[h][(y + dy) * 29 + (x + dx)] * kk[h][dy * 5 + dx];
                    s_full += vv;
                    if (dy >= 1 && dy <= 3 && dx >= 1 && dx <= 3) s_in += vv;
                }
            f0[h] = s_full;
            f1[h] = s_in;
            f2[h] = ss[h][(y + 2) * 29 + (x + 2)] * kk[h][12];
        }
        const int n = b * 625 + p;
        ff[(size_t)kp0 * 40000 + n]         = pack2h(f0[0], f0[1]);
        ff[(size_t)(128 + kp0) * 40000 + n] = pack2h(f1[0], f1[1]);
        ff[(size_t)(256 + kp0) * 40000 + n] = pack2h(f2[0], f2[1]);
    }
}

// ---------------------------------------------------------------------------
// Final 1x1: (B,256,625) x (10,256) + bias -> (B,10,625). grid (B, 5).
// ---------------------------------------------------------------------------
__global__ void conv1x1_out_kernel(const float* __restrict__ in,
                                   const float* __restrict__ w,
                                   const float* __restrict__ bias,
                                   float* __restrict__ out) {
    const int b = blockIdx.x;
    const int chunk = blockIdx.y;

    __shared__ float wsm[COUT_ * HID_];
    for (int i = threadIdx.x; i < COUT_ * HID_; i += blockDim.x) wsm[i] = w[i];
    __syncthreads();

    const float* ib = in + (size_t)b * HID_ * 625;
    float* ob = out + (size_t)b * COUT_ * 625;

    const int pend = min(625, (chunk + 1) * 125);
    for (int p = chunk * 125 + threadIdx.x; p < pend; p += blockDim.x) {
        float acc[COUT_];
#pragma unroll
        for (int o = 0; o < COUT_; o++) acc[o] = bias[o];
        for (int c = 0; c < HID_; c++) {
            float vv = ib[(size_t)c * 625 + p];
#pragma unroll
            for (int o = 0; o < COUT_; o++) acc[o] = fmaf(vv, wsm[o * HID_ + c], acc[o]);
        }
#pragma unroll
        for (int o = 0; o < COUT_; o++) ob[(size_t)o * 625 + p] = acc[o];
    }
}

// ---------------------------------------------------------------------------
extern "C" void kernel_launch(void* const* d_in, const int* in_sizes, int n_in,
                              void* d_out, int out_size) {
    const float* kernel_in = (const float*)d_in[0];
    const float* search_in = (const float*)d_in[1];
    const float* wk  = (const float*)d_in[2];
    const float* bnk = (const float*)d_in[3];
    const float* ws  = (const float*)d_in[4];
    const float* bns = (const float*)d_in[5];
    const float* wd  = (const float*)d_in[6];
    const float* bnd = (const float*)d_in[7];
    const float* wh1 = (const float*)d_in[8];
    const float* bnh = (const float*)d_in[9];
    const float* wh2 = (const float*)d_in[10];
    const float* bh2 = (const float*)d_in[11];
    float* out = (float*)d_out;

    float *kfeat, *sfeat, *h;
    uint4 *wkA, *wsA, *wdA, *wh1A;
    uint32_t *kinF, *sinF, *featF, *f2F;
    cudaGetSymbolAddress((void**)&kfeat, g_kfeat);
    cudaGetSymbolAddress((void**)&sfeat, g_sfeat);
    cudaGetSymbolAddress((void**)&h,     g_h);
    cudaGetSymbolAddress((void**)&wkA, g_wkA);
    cudaGetSymbolAddress((void**)&wsA, g_wsA);
    cudaGetSymbolAddress((void**)&wdA, g_wdA);
    cudaGetSymbolAddress((void**)&wh1A, g_wh1A);
    cudaGetSymbolAddress((void**)&kinF, g_kinF);
    cudaGetSymbolAddress((void**)&sinF, g_sinF);
    cudaGetSymbolAddress((void**)&featF, g_featF);
    cudaGetSymbolAddress((void**)&f2F, g_f2F);

    constexpr int SMEM = 128 * 132 * 4;   // 67584 (B staging 2x18432 B < epi)

    cudaFuncSetAttribute(gemm_f16_kernel<0, 7, 7, 2304, true, 0>,
                         cudaFuncAttributeMaxDynamicSharedMemorySize, SMEM);
    cudaFuncSetAttribute(gemm_f16_kernel<0, 31, 31, 2304, true, 0>,
                         cudaFuncAttributeMaxDynamicSharedMemorySize, SMEM);
    cudaFuncSetAttribute(gemm_f16_kernel<1, 3, 3, 768, false, 1>,
                         cudaFuncAttributeMaxDynamicSharedMemorySize, SMEM);
    cudaFuncSetAttribute(gemm_f16_kernel<1, 3, 3, 256, true, 0>,
                         cudaFuncAttributeMaxDynamicSharedMemorySize, SMEM);

    // #0-#2: dependencies of gemm_s (ncu window = launch index 3)
    prep_in_f16<961><<<(128 * 64 * 961 + 255) / 256, 256>>>(search_in, sinF);   // 0
    prep_w3_frag<<<(16 * 144 * 32 + 255) / 256, 256>>>(ws, wsA);                // 1
    prep_w1_frag<768><<<(16 * 48 * 32 + 255) / 256, 256>>>(wd, wdA);            // 2

    // #3: search branch conv3x3 -> g_sfeat  [PROFILED]
    gemm_f16_kernel<0, 31, 31, 2304, true, 0><<<dim3(421, 2), 256, SMEM>>>(
        sinF, wsA, bns, sfeat, nullptr);

    // remaining preps
    prep_w3_frag<<<(16 * 144 * 32 + 255) / 256, 256>>>(wk, wkA);                // 4
    prep_w1_frag<256><<<(16 * 16 * 32 + 255) / 256, 256>>>(wh1, wh1A);          // 5
    prep_in_f16<49><<<(128 * 64 * 49 + 255) / 256, 256>>>(kernel_in, kinF);     // 6

    // kernel branch conv3x3 -> g_kfeat
    gemm_f16_kernel<0, 7, 7, 2304, true, 0><<<dim3(13, 2), 256, SMEM>>>(
        kinF, wkA, bnk, kfeat, nullptr);
    // xcorr -> packed featF (single fp16)
    multixcorr_kernel<<<dim3(128, B_), 256>>>(sfeat, kfeat, featF);
    // wd + bn -> packed f2F
    gemm_f16_kernel<1, 3, 3, 768, false, 1><<<dim3(313, 2), 256, SMEM>>>(
        featF, wdA, bnd, nullptr, (uint16_t*)f2F);
    // wh1 + bn + relu -> g_h
    gemm_f16_kernel<1, 3, 3, 256, true, 0><<<dim3(313, 2), 256, SMEM>>>(
        f2F, wh1A, bnh, h, nullptr);
    // wh2 + bias -> out
    conv1x1_out_kernel<<<dim3(B_, 5), 128>>>(h, wh2, bh2, out);
}